// round 3
// baseline (speedup 1.0000x reference)
#include <cuda_runtime.h>
#include <math.h>

// ---------------- problem constants ----------------
#define B_    2
#define C_    48
#define T_    16
#define H_    64
#define W_    64
#define N_    65536          // T*H*W per batch
#define HEADS_ 4
#define NSPLIT 64

typedef unsigned long long u64;

// ---------------- f32x2 packed helpers ----------------
__device__ __forceinline__ u64 pack2(float lo, float hi) {
    u64 r; asm("mov.b64 %0,{%1,%2};" : "=l"(r) : "f"(lo), "f"(hi)); return r;
}
__device__ __forceinline__ void unpack2(u64 v, float& lo, float& hi) {
    asm("mov.b64 {%0,%1},%2;" : "=f"(lo), "=f"(hi) : "l"(v));
}
__device__ __forceinline__ u64 fma2(u64 a, u64 b, u64 c) {
    u64 d; asm("fma.rn.f32x2 %0,%1,%2,%3;" : "=l"(d) : "l"(a), "l"(b), "l"(c)); return d;
}

// ---------------- scratch (static device globals; no allocs) ----------------
__device__ float g_qkv [(size_t)B_*576*N_];
__device__ float g_qkv2[(size_t)B_*576*N_];
__device__ float g_t192[(size_t)B_*192*N_];
__device__ float g_ln  [(size_t)B_*C_*N_];
__device__ float g_part[(size_t)NSPLIT*B_*HEADS_*48*48];
__device__ float g_attn[(size_t)B_*HEADS_*48*48];
__device__ float g_sumsq[(size_t)B_*384];

// ---------------- LayerNorm over channel dim (+ optional sumsq zeroing) ----------------
__global__ void ln_kernel(const float* __restrict__ x, const float* __restrict__ w,
                          const float* __restrict__ b, float* __restrict__ y,
                          float* __restrict__ zerobuf) {
    int idx = blockIdx.x * blockDim.x + threadIdx.x;
    if (zerobuf && idx < B_ * 384) zerobuf[idx] = 0.f;
    if (idx >= B_ * N_) return;
    int bi = idx / N_, n = idx - bi * N_;
    const float* xp = x + (size_t)bi * C_ * N_ + n;
    float v[C_];
    float mu = 0.f;
#pragma unroll
    for (int c = 0; c < C_; c++) { v[c] = xp[(size_t)c * N_]; mu += v[c]; }
    mu *= (1.f / C_);
    float var = 0.f;
#pragma unroll
    for (int c = 0; c < C_; c++) { float d = v[c] - mu; var += d * d; }
    var *= (1.f / C_);
    float inv = rsqrtf(var + 1e-5f);
    float* yp = y + (size_t)bi * C_ * N_ + n;
#pragma unroll
    for (int c = 0; c < C_; c++) yp[(size_t)c * N_] = (v[c] - mu) * inv * w[c] + b[c];
}

// ---------------- 1x1x1 conv: CO_TILE=16 outputs x NPT=4 positions, f32x2 ----------------
template<int CIN>
__global__ void __launch_bounds__(128) conv1x1p_kernel(
        const float* __restrict__ in, const float* __restrict__ wgt,
        const float* __restrict__ bias, const float* __restrict__ res,
        float* __restrict__ out, int cout) {
    __shared__ u64 ws2[16 * CIN];
    int tid = threadIdx.x;
    int cb = blockIdx.y * 16;
    int b  = blockIdx.z;
    for (int i = tid; i < 16 * CIN; i += 128) {
        float wv = wgt[(size_t)(cb + i / CIN) * CIN + (i % CIN)];
        ws2[i] = pack2(wv, wv);
    }
    __syncthreads();
    int n0 = (blockIdx.x * 128 + tid) * 4;
    u64 acc[16][2];
#pragma unroll
    for (int o = 0; o < 16; o++) {
        float bvv = bias[cb + o];
        acc[o][0] = acc[o][1] = pack2(bvv, bvv);
    }
    const float* ip = in + (size_t)b * CIN * N_ + n0;
#pragma unroll 4
    for (int c = 0; c < CIN; c++) {
        float4 xv = *reinterpret_cast<const float4*>(ip + (size_t)c * N_);
        u64 p0 = pack2(xv.x, xv.y), p1 = pack2(xv.z, xv.w);
#pragma unroll
        for (int o = 0; o < 16; o++) {
            u64 wv = ws2[o * CIN + c];
            acc[o][0] = fma2(wv, p0, acc[o][0]);
            acc[o][1] = fma2(wv, p1, acc[o][1]);
        }
    }
    float* op = out + ((size_t)b * cout + cb) * N_ + n0;
    if (res) {
        const float* rp = res + ((size_t)b * cout + cb) * N_ + n0;
#pragma unroll
        for (int o = 0; o < 16; o++) {
            float4 rv = *reinterpret_cast<const float4*>(rp + (size_t)o * N_);
            float a0, a1, a2, a3;
            unpack2(acc[o][0], a0, a1);
            unpack2(acc[o][1], a2, a3);
            *reinterpret_cast<float4*>(op + (size_t)o * N_) =
                make_float4(a0 + rv.x, a1 + rv.y, a2 + rv.z, a3 + rv.w);
        }
    } else {
#pragma unroll
        for (int o = 0; o < 16; o++) {
            float a0, a1, a2, a3;
            unpack2(acc[o][0], a0, a1);
            unpack2(acc[o][1], a2, a3);
            *reinterpret_cast<float4*>(op + (size_t)o * N_) = make_float4(a0, a1, a2, a3);
        }
    }
}

// ---------------- depthwise 3x3x3 accumulate into 4h x 8w packed tile ----------------
__device__ __forceinline__ void dw_accum(const float* __restrict__ ip,
                                         const float* __restrict__ wb,
                                         int t, int h0, int w0, u64 acc[16]) {
#pragma unroll
    for (int kd = 0; kd < 3; kd++) {
        int tt = t + kd - 1;
        if ((unsigned)tt >= (unsigned)T_) continue;
        u64 wk2[9];
#pragma unroll
        for (int j = 0; j < 9; j++) { float wv = wb[kd * 9 + j]; wk2[j] = pack2(wv, wv); }
        const float* pl = ip + (size_t)tt * H_ * W_;
#pragma unroll
        for (int r = 0; r < 6; r++) {
            int hh = h0 - 1 + r;
            if ((unsigned)hh >= (unsigned)H_) continue;
            const float* rowp = pl + hh * W_ + w0;
            float e0 = (w0 > 0) ? rowp[-1] : 0.f;
            float4 m0 = *reinterpret_cast<const float4*>(rowp);
            float4 m1 = *reinterpret_cast<const float4*>(rowp + 4);
            float e9 = (w0 + 8 < W_) ? rowp[8] : 0.f;
            u64 pe[5], po[4];
            pe[0] = pack2(e0,   m0.x);
            pe[1] = pack2(m0.y, m0.z);
            pe[2] = pack2(m0.w, m1.x);
            pe[3] = pack2(m1.y, m1.z);
            pe[4] = pack2(m1.w, e9);
            po[0] = pack2(m0.x, m0.y);
            po[1] = pack2(m0.z, m0.w);
            po[2] = pack2(m1.x, m1.y);
            po[3] = pack2(m1.z, m1.w);
#pragma unroll
            for (int kh = 0; kh < 3; kh++) {
                int oh = r - kh;
                if (oh < 0 || oh > 3) continue;   // compile-time
                u64 w0k = wk2[kh * 3 + 0];
                u64 w1k = wk2[kh * 3 + 1];
                u64 w2k = wk2[kh * 3 + 2];
#pragma unroll
                for (int p = 0; p < 4; p++) {
                    u64 a = acc[oh * 4 + p];
                    a = fma2(w0k, pe[p],     a);
                    a = fma2(w1k, po[p],     a);
                    a = fma2(w2k, pe[p + 1], a);
                    acc[oh * 4 + p] = a;
                }
            }
        }
    }
}

// ---------------- grouped 3x3x3 conv (576 ch, 4-in/4-out per group) + sumsq ----------------
__global__ void __launch_bounds__(128) gdw576_kernel(
        const float* __restrict__ in, const float* __restrict__ wgt,
        const float* __restrict__ bias, float* __restrict__ out,
        float* __restrict__ sumsq) {
    int tid = threadIdx.x;
    int wq = tid & 7, hq = tid >> 3;        // block = one (b, o, t)
    long bidx = blockIdx.x;                 // B*576*16
    int t = (int)(bidx & 15);
    int o = (int)((bidx >> 4) % 576);
    int b = (int)(bidx / (16 * 576));
    int w0 = wq * 8, h0 = hq * 4;
    int cbase = (o >> 2) << 2;

    float bv = bias[o];
    u64 acc[16];
#pragma unroll
    for (int i = 0; i < 16; i++) acc[i] = pack2(bv, bv);

    const float* wb = wgt + (size_t)o * 4 * 27;
#pragma unroll 1
    for (int ci = 0; ci < 4; ci++)
        dw_accum(in + (size_t)(b * 576 + cbase + ci) * (T_ * H_ * W_),
                 wb + ci * 27, t, h0, w0, acc);

    float* op = out + ((size_t)(b * 576 + o) * T_ + t) * H_ * W_;
    float ssq = 0.f;
#pragma unroll
    for (int oh = 0; oh < 4; oh++) {
        float v0, v1, v2, v3, v4, v5, v6, v7;
        unpack2(acc[oh * 4 + 0], v0, v1);
        unpack2(acc[oh * 4 + 1], v2, v3);
        unpack2(acc[oh * 4 + 2], v4, v5);
        unpack2(acc[oh * 4 + 3], v6, v7);
        *reinterpret_cast<float4*>(op + (h0 + oh) * W_ + w0)     = make_float4(v0, v1, v2, v3);
        *reinterpret_cast<float4*>(op + (h0 + oh) * W_ + w0 + 4) = make_float4(v4, v5, v6, v7);
        ssq += v0*v0 + v1*v1 + v2*v2 + v3*v3 + v4*v4 + v5*v5 + v6*v6 + v7*v7;
    }
    if (o < 384) atomicAdd(&sumsq[b * 384 + o], ssq);
}

// ---------------- FFN depthwise 3x3x3 + GELU gate fused ----------------
__global__ void __launch_bounds__(128) ffn_dw_gate_kernel(
        const float* __restrict__ in,   // 192 channels
        const float* __restrict__ wgt, const float* __restrict__ bias,
        float* __restrict__ out) {      // 96 channels (gated)
    int tid = threadIdx.x;
    int wq = tid & 7, hq = tid >> 3;
    long bidx = blockIdx.x;                 // B*96*16
    int t = (int)(bidx & 15);
    int c = (int)((bidx >> 4) % 96);
    int b = (int)(bidx / (16 * 96));
    int w0 = wq * 8, h0 = hq * 4;

    float b1 = bias[c], b2v = bias[c + 96];
    u64 a1[16], a2[16];
#pragma unroll
    for (int i = 0; i < 16; i++) { a1[i] = pack2(b1, b1); a2[i] = pack2(b2v, b2v); }

    dw_accum(in + (size_t)(b * 192 + c)      * (T_ * H_ * W_), wgt + (size_t)c * 27,        t, h0, w0, a1);
    dw_accum(in + (size_t)(b * 192 + 96 + c) * (T_ * H_ * W_), wgt + (size_t)(96 + c) * 27, t, h0, w0, a2);

    float* op = out + ((size_t)(b * 96 + c) * T_ + t) * H_ * W_;
#pragma unroll
    for (int oh = 0; oh < 4; oh++) {
        float z1[8], z2[8];
        unpack2(a1[oh*4+0], z1[0], z1[1]); unpack2(a1[oh*4+1], z1[2], z1[3]);
        unpack2(a1[oh*4+2], z1[4], z1[5]); unpack2(a1[oh*4+3], z1[6], z1[7]);
        unpack2(a2[oh*4+0], z2[0], z2[1]); unpack2(a2[oh*4+1], z2[2], z2[3]);
        unpack2(a2[oh*4+2], z2[4], z2[5]); unpack2(a2[oh*4+3], z2[6], z2[7]);
        float g[8];
#pragma unroll
        for (int j = 0; j < 8; j++) {
            float a = z1[j];
            g[j] = 0.5f * a * (1.f + erff(a * 0.70710678118654752f)) * z2[j];
        }
        *reinterpret_cast<float4*>(op + (h0 + oh) * W_ + w0)     = make_float4(g[0], g[1], g[2], g[3]);
        *reinterpret_cast<float4*>(op + (h0 + oh) * W_ + w0 + 4) = make_float4(g[4], g[5], g[6], g[7]);
    }
}

// ---------------- q·k^T partials: 48x48 GEMM over a 1024-slice of N ----------------
__global__ void qk_kernel(const float* __restrict__ qkv2, float* __restrict__ part) {
    int ns = blockIdx.x, h = blockIdx.y, b = blockIdx.z;
    __shared__ float qs[48][65];
    __shared__ float ks[48][65];
    int tid = threadIdx.x;
    int tx = tid & 15, ty = tid >> 4;
    int c0 = tx * 3, d0 = ty * 3;
    float acc[3][3] = {};
    int nbase = ns * (N_ / NSPLIT);
    const float* qbase = qkv2 + (size_t)(b * 576 + h * 48) * N_;
    const float* kbase = qkv2 + (size_t)(b * 576 + 192 + h * 48) * N_;
    for (int off = 0; off < N_ / NSPLIT; off += 64) {
        for (int i = tid; i < 48 * 64; i += 256) {
            int c = i >> 6, nn = i & 63;
            qs[c][nn] = qbase[(size_t)c * N_ + nbase + off + nn];
            ks[c][nn] = kbase[(size_t)c * N_ + nbase + off + nn];
        }
        __syncthreads();
#pragma unroll 8
        for (int nn = 0; nn < 64; nn++) {
            float q0 = qs[c0][nn], q1 = qs[c0 + 1][nn], q2 = qs[c0 + 2][nn];
            float k0 = ks[d0][nn], k1 = ks[d0 + 1][nn], k2 = ks[d0 + 2][nn];
            acc[0][0] = fmaf(q0, k0, acc[0][0]);
            acc[0][1] = fmaf(q0, k1, acc[0][1]);
            acc[0][2] = fmaf(q0, k2, acc[0][2]);
            acc[1][0] = fmaf(q1, k0, acc[1][0]);
            acc[1][1] = fmaf(q1, k1, acc[1][1]);
            acc[1][2] = fmaf(q1, k2, acc[1][2]);
            acc[2][0] = fmaf(q2, k0, acc[2][0]);
            acc[2][1] = fmaf(q2, k1, acc[2][1]);
            acc[2][2] = fmaf(q2, k2, acc[2][2]);
        }
        __syncthreads();
    }
    float* pp = part + (((size_t)ns * B_ + b) * HEADS_ + h) * 2304;
#pragma unroll
    for (int i = 0; i < 3; i++)
#pragma unroll
        for (int j = 0; j < 3; j++) pp[(c0 + i) * 48 + d0 + j] = acc[i][j];
}

// ---------------- reduce partials, scale by rsqrt(sumsq) & temperature, softmax ----------------
__global__ void softmax_kernel(const float* __restrict__ part, const float* __restrict__ sumsq,
                               const float* __restrict__ temp, float* __restrict__ attn) {
    int c = blockIdx.x, h = blockIdx.y, b = blockIdx.z;
    int d = threadIdx.x;
    __shared__ float sv[48];
    __shared__ float m_s, sum_s;
    float s = 0.f;
    if (d < 48) {
        const float* pp = part + ((size_t)b * HEADS_ + h) * 2304 + c * 48 + d;
        const size_t stride = (size_t)B_ * HEADS_ * 2304;
        for (int p = 0; p < NSPLIT; p++) s += pp[(size_t)p * stride];
        float rq = 1.f / fmaxf(sqrtf(sumsq[b * 384 + h * 48 + c]), 1e-12f);
        float rk = 1.f / fmaxf(sqrtf(sumsq[b * 384 + 192 + h * 48 + d]), 1e-12f);
        s *= rq * rk * temp[h];
        sv[d] = s;
    }
    __syncthreads();
    if (threadIdx.x == 0) {
        float m = sv[0];
        for (int i = 1; i < 48; i++) m = fmaxf(m, sv[i]);
        m_s = m;
    }
    __syncthreads();
    float e = 0.f;
    if (d < 48) { e = expf(s - m_s); sv[d] = e; }
    __syncthreads();
    if (threadIdx.x == 0) {
        float t2 = 0.f;
        for (int i = 0; i < 48; i++) t2 += sv[i];
        sum_s = t2;
    }
    __syncthreads();
    if (d < 48) attn[(((size_t)b * HEADS_ + h) * 48 + c) * 48 + d] = e / sum_s;
}

// ---------------- out = attn @ v  (NPT=2, f32x2) ----------------
__global__ void av_kernel(const float* __restrict__ qkv2, const float* __restrict__ attn,
                          float* __restrict__ out) {
    int h = blockIdx.y, b = blockIdx.z;
    __shared__ float2 a2[48 * 48];
    int tid = threadIdx.x;
    for (int i = tid; i < 2304; i += 128) {
        float a = attn[((size_t)b * HEADS_ + h) * 2304 + i];
        a2[i] = make_float2(a, a);
    }
    __syncthreads();
    int n0 = (blockIdx.x * 128 + tid) * 2;
    const float* vb = qkv2 + (size_t)(b * 576 + 384 + h * 48) * N_ + n0;
    u64 acc[48];
#pragma unroll
    for (int c = 0; c < 48; c++) acc[c] = 0ull;
    const u64* as = reinterpret_cast<const u64*>(a2);
#pragma unroll 2
    for (int d = 0; d < 48; d++) {
        u64 pv = *reinterpret_cast<const u64*>(vb + (size_t)d * N_);
#pragma unroll
        for (int c = 0; c < 48; c++)
            acc[c] = fma2(as[c * 48 + d], pv, acc[c]);
    }
    float* op = out + (size_t)(b * 192 + h * 48) * N_ + n0;
#pragma unroll
    for (int c = 0; c < 48; c++)
        *reinterpret_cast<u64*>(op + (size_t)c * N_) = acc[c];
}

// ---------------- launcher ----------------
extern "C" void kernel_launch(void* const* d_in, const int* in_sizes, int n_in,
                              void* d_out, int out_size) {
    (void)in_sizes; (void)n_in; (void)out_size;
    const float* x      = (const float*)d_in[0];
    const float* ln1_w  = (const float*)d_in[1];
    const float* ln1_b  = (const float*)d_in[2];
    const float* qkv_w  = (const float*)d_in[3];
    const float* qkv_b  = (const float*)d_in[4];
    const float* qkvdw_w= (const float*)d_in[5];
    const float* qkvdw_b= (const float*)d_in[6];
    const float* temper = (const float*)d_in[7];
    const float* proj_w = (const float*)d_in[8];
    const float* proj_b = (const float*)d_in[9];
    const float* ln2_w  = (const float*)d_in[10];
    const float* ln2_b  = (const float*)d_in[11];
    const float* pin_w  = (const float*)d_in[12];
    const float* pin_b  = (const float*)d_in[13];
    const float* dw_w   = (const float*)d_in[14];
    const float* dw_b   = (const float*)d_in[15];
    const float* pout_w = (const float*)d_in[16];
    const float* pout_b = (const float*)d_in[17];
    float* out = (float*)d_out;

    float *qkv, *qkv2, *t192, *ln, *part, *attn, *sumsq;
    cudaGetSymbolAddress((void**)&qkv,  g_qkv);
    cudaGetSymbolAddress((void**)&qkv2, g_qkv2);
    cudaGetSymbolAddress((void**)&t192, g_t192);
    cudaGetSymbolAddress((void**)&ln,   g_ln);
    cudaGetSymbolAddress((void**)&part, g_part);
    cudaGetSymbolAddress((void**)&attn, g_attn);
    cudaGetSymbolAddress((void**)&sumsq,g_sumsq);

    // ---- attention branch ----
    ln_kernel<<<(B_ * N_) / 256, 256>>>(x, ln1_w, ln1_b, ln, sumsq);

    conv1x1p_kernel<48><<<dim3(N_ / 512, 576 / 16, B_), 128>>>(ln, qkv_w, qkv_b, nullptr, qkv, 576);

    gdw576_kernel<<<B_ * 576 * T_, 128>>>(qkv, qkvdw_w, qkvdw_b, qkv2, sumsq);

    qk_kernel<<<dim3(NSPLIT, HEADS_, B_), 256>>>(qkv2, part);

    softmax_kernel<<<dim3(48, HEADS_, B_), 64>>>(part, sumsq, temper, attn);

    av_kernel<<<dim3(N_ / 256, HEADS_, B_), 128>>>(qkv2, attn, t192);

    conv1x1p_kernel<192><<<dim3(N_ / 512, 48 / 16, B_), 128>>>(t192, proj_w, proj_b, x, out, 48);

    // ---- FFN branch ----
    ln_kernel<<<(B_ * N_) / 256, 256>>>(out, ln2_w, ln2_b, ln, nullptr);

    conv1x1p_kernel<48><<<dim3(N_ / 512, 192 / 16, B_), 128>>>(ln, pin_w, pin_b, nullptr, t192, 192);

    ffn_dw_gate_kernel<<<B_ * 96 * T_, 128>>>(t192, dw_w, dw_b, qkv);

    conv1x1p_kernel<96><<<dim3(N_ / 512, 48 / 16, B_), 128>>>(qkv, pout_w, pout_b, out, out, 48);
}